// round 1
// baseline (speedup 1.0000x reference)
#include <cuda_runtime.h>
#include <math.h>

#define BB 2
#define SS 2048
#define DD 1024
#define HH 16
#define DHH 64
#define MTOT (BB*SS)   // 4096

// Scratch (alloc-free rule): 4 buffers of B*S*D floats = 64 MB total
__device__ float g_Qp[BB*SS*DD];
__device__ float g_Kp[BB*SS*DD];
__device__ float g_Vp[BB*SS*DD];
__device__ float g_X [BB*SS*DD];

// ---------------------------------------------------------------------------
// C[M,N] = A[M,K] @ W[K,N] + bias[N]    (all fp32, row-major)
// 128x128 tile, BK=16, 256 threads, 8x8 micro-tile per thread
// ---------------------------------------------------------------------------
__global__ __launch_bounds__(256) void gemm_bias_kernel(
    const float* __restrict__ A, const float* __restrict__ W,
    const float* __restrict__ bias, float* __restrict__ C,
    int M, int N, int K)
{
    __shared__ float As[16][128];   // transposed A tile: As[k][m]
    __shared__ float Bs[16][128];   // Bs[k][n]

    const int tid = threadIdx.x;
    const int tx = tid & 15;
    const int ty = tid >> 4;
    const int bm = blockIdx.y * 128;
    const int bn = blockIdx.x * 128;

    float acc[8][8];
    #pragma unroll
    for (int i = 0; i < 8; ++i)
        #pragma unroll
        for (int j = 0; j < 8; ++j) acc[i][j] = 0.f;

    for (int kk = 0; kk < K; kk += 16) {
        // Load A tile 128x16 (transpose into As[k][m])
        #pragma unroll
        for (int u = 0; u < 2; ++u) {
            int f  = tid * 2 + u;        // 0..511
            int r  = f >> 2;             // 0..127
            int c4 = f & 3;              // 0..3
            float4 a = *(const float4*)&A[(size_t)(bm + r) * K + kk + c4 * 4];
            As[c4*4+0][r] = a.x;
            As[c4*4+1][r] = a.y;
            As[c4*4+2][r] = a.z;
            As[c4*4+3][r] = a.w;
        }
        // Load B tile 16x128
        #pragma unroll
        for (int u = 0; u < 2; ++u) {
            int f  = tid * 2 + u;        // 0..511
            int r  = f >> 5;             // 0..15
            int c4 = f & 31;             // 0..31
            *(float4*)&Bs[r][c4*4] =
                *(const float4*)&W[(size_t)(kk + r) * N + bn + c4 * 4];
        }
        __syncthreads();

        #pragma unroll
        for (int k = 0; k < 16; ++k) {
            float a[8], b[8];
            *(float4*)&a[0] = *(const float4*)&As[k][ty*8];
            *(float4*)&a[4] = *(const float4*)&As[k][ty*8+4];
            *(float4*)&b[0] = *(const float4*)&Bs[k][tx*8];
            *(float4*)&b[4] = *(const float4*)&Bs[k][tx*8+4];
            #pragma unroll
            for (int i = 0; i < 8; ++i)
                #pragma unroll
                for (int j = 0; j < 8; ++j)
                    acc[i][j] += a[i] * b[j];
        }
        __syncthreads();
    }

    #pragma unroll
    for (int i = 0; i < 8; ++i) {
        int row = bm + ty*8 + i;
        #pragma unroll
        for (int j4 = 0; j4 < 2; ++j4) {
            int col = bn + tx*8 + j4*4;
            float4 bb = *(const float4*)&bias[col];
            float4 o;
            o.x = acc[i][j4*4+0] + bb.x;
            o.y = acc[i][j4*4+1] + bb.y;
            o.z = acc[i][j4*4+2] + bb.z;
            o.w = acc[i][j4*4+3] + bb.w;
            *(float4*)&C[(size_t)row * N + col] = o;
        }
    }
}

// ---------------------------------------------------------------------------
// Flash attention (fp32, online softmax, NO 1/sqrt(dk) scaling — matches ref).
// grid: (S/64, B*H). block: 256 threads (16x16), 4x4 micro-tile.
// Output written with the reference's buggy swapaxes(0,1).reshape layout:
//   X[((h*B + b)*S + s)*DH + d]
// ---------------------------------------------------------------------------
#define QS_PITCH 68
#define PS_PITCH 68

__global__ __launch_bounds__(256) void attn_kernel(
    const float* __restrict__ Qp, const float* __restrict__ Kp,
    const float* __restrict__ Vp, float* __restrict__ X)
{
    extern __shared__ float sm[];
    float* Qs  = sm;                        // 64 x 68
    float* Kst = Qs  + 64 * QS_PITCH;       // 64 x 64  [d][key]
    float* Vs  = Kst + 64 * 64;             // 64 x 64  [key][d]
    float* Ps  = Vs  + 64 * 64;             // 64 x 68

    const int tid = threadIdx.x;
    const int tx = tid & 15;
    const int ty = tid >> 4;
    const int q0 = blockIdx.x * 64;
    const int bh = blockIdx.y;
    const int b  = bh >> 4;   // / HH
    const int h  = bh & 15;   // % HH

    const float* Qbase = Qp + (size_t)b * SS * DD + h * DHH;
    const float* Kbase = Kp + (size_t)b * SS * DD + h * DHH;
    const float* Vbase = Vp + (size_t)b * SS * DD + h * DHH;

    // Load Q tile (64 rows x 64 dims)
    #pragma unroll
    for (int u = 0; u < 4; ++u) {
        int f  = tid + u * 256;   // 0..1023
        int r  = f >> 4;          // 0..63
        int c4 = f & 15;          // 0..15
        float4 q4 = *(const float4*)&Qbase[(size_t)(q0 + r) * DD + c4 * 4];
        *(float4*)&Qs[r * QS_PITCH + c4 * 4] = q4;
    }

    float m_i[4], l_i[4], o[4][4];
    #pragma unroll
    for (int i = 0; i < 4; ++i) {
        m_i[i] = -1e30f; l_i[i] = 0.f;
        #pragma unroll
        for (int j = 0; j < 4; ++j) o[i][j] = 0.f;
    }

    for (int kt = 0; kt < SS / 64; ++kt) {
        // Load K (transposed into Kst[d][key]) and V (Vs[key][d])
        #pragma unroll
        for (int u = 0; u < 4; ++u) {
            int f  = tid + u * 256;
            int r  = f >> 4;        // key 0..63
            int c4 = f & 15;
            float4 k4 = *(const float4*)&Kbase[(size_t)(kt*64 + r) * DD + c4 * 4];
            Kst[(c4*4+0)*64 + r] = k4.x;
            Kst[(c4*4+1)*64 + r] = k4.y;
            Kst[(c4*4+2)*64 + r] = k4.z;
            Kst[(c4*4+3)*64 + r] = k4.w;
            float4 v4 = *(const float4*)&Vbase[(size_t)(kt*64 + r) * DD + c4 * 4];
            *(float4*)&Vs[r * 64 + c4 * 4] = v4;
        }
        __syncthreads();

        // S tile: s[i][j] = dot(Q[row_i], K[col_j])  — no scaling
        float s[4][4];
        #pragma unroll
        for (int i = 0; i < 4; ++i)
            #pragma unroll
            for (int j = 0; j < 4; ++j) s[i][j] = 0.f;

        #pragma unroll 8
        for (int d = 0; d < 64; ++d) {
            float4 kv = *(const float4*)&Kst[d * 64 + tx * 4];
            #pragma unroll
            for (int i = 0; i < 4; ++i) {
                float qv = Qs[(ty*4 + i) * QS_PITCH + d];
                s[i][0] += qv * kv.x;
                s[i][1] += qv * kv.y;
                s[i][2] += qv * kv.z;
                s[i][3] += qv * kv.w;
            }
        }

        // Online softmax update (row stats reduced across the 16 tx lanes)
        #pragma unroll
        for (int i = 0; i < 4; ++i) {
            float mx = fmaxf(fmaxf(s[i][0], s[i][1]), fmaxf(s[i][2], s[i][3]));
            #pragma unroll
            for (int off = 1; off < 16; off <<= 1)
                mx = fmaxf(mx, __shfl_xor_sync(0xffffffffu, mx, off));
            float m_new = fmaxf(m_i[i], mx);
            float scale = __expf(m_i[i] - m_new);
            float p0 = __expf(s[i][0] - m_new);
            float p1 = __expf(s[i][1] - m_new);
            float p2 = __expf(s[i][2] - m_new);
            float p3 = __expf(s[i][3] - m_new);
            float ps = p0 + p1 + p2 + p3;
            #pragma unroll
            for (int off = 1; off < 16; off <<= 1)
                ps += __shfl_xor_sync(0xffffffffu, ps, off);
            l_i[i] = l_i[i] * scale + ps;
            m_i[i] = m_new;
            #pragma unroll
            for (int j = 0; j < 4; ++j) o[i][j] *= scale;
            float4 p4 = make_float4(p0, p1, p2, p3);
            *(float4*)&Ps[(ty*4 + i) * PS_PITCH + tx * 4] = p4;
        }
        __syncthreads();

        // O += P @ V
        #pragma unroll 8
        for (int k = 0; k < 64; ++k) {
            float4 vv = *(const float4*)&Vs[k * 64 + tx * 4];
            #pragma unroll
            for (int i = 0; i < 4; ++i) {
                float pv = Ps[(ty*4 + i) * PS_PITCH + k];
                o[i][0] += pv * vv.x;
                o[i][1] += pv * vv.y;
                o[i][2] += pv * vv.z;
                o[i][3] += pv * vv.w;
            }
        }
        __syncthreads();
    }

    // Normalize and write with the reference's buggy permutation layout
    #pragma unroll
    for (int i = 0; i < 4; ++i) {
        int r = ty*4 + i;
        float inv = 1.0f / l_i[i];
        float4 ov = make_float4(o[i][0]*inv, o[i][1]*inv, o[i][2]*inv, o[i][3]*inv);
        size_t idx = (((size_t)(h * BB + b) * SS) + (q0 + r)) * DHH + tx * 4;
        *(float4*)&X[idx] = ov;
    }
}

#define ATTN_SMEM ((64*QS_PITCH + 64*64 + 64*64 + 64*PS_PITCH) * (int)sizeof(float))

extern "C" void kernel_launch(void* const* d_in, const int* in_sizes, int n_in,
                              void* d_out, int out_size)
{
    const float* q  = (const float*)d_in[0];
    const float* k  = (const float*)d_in[1];
    const float* v  = (const float*)d_in[2];
    const float* wq = (const float*)d_in[3];
    const float* bq = (const float*)d_in[4];
    const float* wk = (const float*)d_in[5];
    const float* bk = (const float*)d_in[6];
    const float* wv = (const float*)d_in[7];
    const float* bv = (const float*)d_in[8];
    const float* wo = (const float*)d_in[9];
    const float* bo = (const float*)d_in[10];
    float* out = (float*)d_out;

    float *Qp, *Kp, *Vp, *X;
    cudaGetSymbolAddress((void**)&Qp, g_Qp);
    cudaGetSymbolAddress((void**)&Kp, g_Kp);
    cudaGetSymbolAddress((void**)&Vp, g_Vp);
    cudaGetSymbolAddress((void**)&X,  g_X);

    cudaFuncSetAttribute(attn_kernel,
                         cudaFuncAttributeMaxDynamicSharedMemorySize, ATTN_SMEM);

    dim3 gGrid(DD / 128, MTOT / 128);   // (8, 32)
    dim3 gBlk(256);

    // Projections
    gemm_bias_kernel<<<gGrid, gBlk>>>(q, wq, bq, Qp, MTOT, DD, DD);
    gemm_bias_kernel<<<gGrid, gBlk>>>(k, wk, bk, Kp, MTOT, DD, DD);
    gemm_bias_kernel<<<gGrid, gBlk>>>(v, wv, bv, Vp, MTOT, DD, DD);

    // Attention
    dim3 aGrid(SS / 64, BB * HH);       // (32, 32)
    attn_kernel<<<aGrid, gBlk, ATTN_SMEM>>>(Qp, Kp, Vp, X);

    // Output projection (reads X in the reference's reshaped order)
    gemm_bias_kernel<<<gGrid, gBlk>>>(X, wo, bo, out, MTOT, DD, DD);
}

// round 3
// speedup vs baseline: 1.3044x; 1.3044x over previous
#include <cuda_runtime.h>
#include <cuda_bf16.h>
#include <cstdint>
#include <math.h>

#define BB 2
#define SS 2048
#define DD 1024
#define HH 16
#define DHH 64
#define MTOT (BB*SS)   // 4096

// Scratch (alloc-free rule)
__device__ __align__(256) float g_Qp[BB*SS*DD];
__device__ __align__(256) float g_Kp[BB*SS*DD];
__device__ __align__(256) float g_Vp[BB*SS*DD];
__device__ __align__(256) float g_X [BB*SS*DD];
__device__ __align__(256) __nv_bfloat16 g_Whi[4][DD*DD];  // K-major [n][k]
__device__ __align__(256) __nv_bfloat16 g_Wlo[4][DD*DD];
__device__ __align__(256) __nv_bfloat16 g_Ahi[MTOT*DD];
__device__ __align__(256) __nv_bfloat16 g_Alo[MTOT*DD];

// ============================================================================
// helpers
// ============================================================================
__device__ __forceinline__ uint32_t smem_u32(const void* p) {
    uint32_t a;
    asm("{ .reg .u64 t; cvta.to.shared.u64 t, %1; cvt.u32.u64 %0, t; }"
        : "=r"(a) : "l"(p));
    return a;
}
__device__ __forceinline__ void cp_async16(uint32_t dst, const void* src) {
    asm volatile("cp.async.cg.shared.global [%0], [%1], 16;" :: "r"(dst), "l"(src));
}
#define CP_COMMIT() asm volatile("cp.async.commit_group;" ::: "memory")

#define MMA_BF16(c, a, b) \
    asm volatile("mma.sync.aligned.m16n8k16.row.col.f32.bf16.bf16.f32 " \
        "{%0,%1,%2,%3}, {%4,%5,%6,%7}, {%8,%9}, {%0,%1,%2,%3};" \
        : "+f"((c)[0]), "+f"((c)[1]), "+f"((c)[2]), "+f"((c)[3]) \
        : "r"((a)[0]), "r"((a)[1]), "r"((a)[2]), "r"((a)[3]), \
          "r"((b)[0]), "r"((b)[1]))

// ============================================================================
// Weight transpose + bf16 hi/lo split:  Whi/Wlo[n*K + k] = split(W[k*N + n])
// ============================================================================
__global__ __launch_bounds__(256) void trans_split_kernel(
    const float* __restrict__ in,
    __nv_bfloat16* __restrict__ hi, __nv_bfloat16* __restrict__ lo)
{
    __shared__ float t[32][33];
    int x = blockIdx.x * 32 + threadIdx.x;
    int y = blockIdx.y * 32 + threadIdx.y;
    #pragma unroll
    for (int j = 0; j < 32; j += 8)
        t[threadIdx.y + j][threadIdx.x] = in[(size_t)(y + j) * DD + x];
    __syncthreads();
    int x2 = blockIdx.y * 32 + threadIdx.x;   // k
    int y2 = blockIdx.x * 32 + threadIdx.y;   // n
    #pragma unroll
    for (int j = 0; j < 32; j += 8) {
        float w = t[threadIdx.x][threadIdx.y + j];
        __nv_bfloat16 h = __float2bfloat16_rn(w);
        __nv_bfloat16 l = __float2bfloat16_rn(w - __bfloat162float(h));
        hi[(size_t)(y2 + j) * DD + x2] = h;
        lo[(size_t)(y2 + j) * DD + x2] = l;
    }
}

// ============================================================================
// Activation bf16 hi/lo split (elementwise, vectorized)
// ============================================================================
__global__ __launch_bounds__(256) void split_kernel(
    const float* __restrict__ a,
    __nv_bfloat16* __restrict__ hi, __nv_bfloat16* __restrict__ lo, int n4)
{
    int i = blockIdx.x * blockDim.x + threadIdx.x;
    if (i >= n4) return;
    float4 v = ((const float4*)a)[i];
    __nv_bfloat16 hx = __float2bfloat16_rn(v.x);
    __nv_bfloat16 hy = __float2bfloat16_rn(v.y);
    __nv_bfloat16 hz = __float2bfloat16_rn(v.z);
    __nv_bfloat16 hw = __float2bfloat16_rn(v.w);
    __nv_bfloat162 h0; h0.x = hx; h0.y = hy;
    __nv_bfloat162 h1; h1.x = hz; h1.y = hw;
    __nv_bfloat162 l0, l1;
    l0.x = __float2bfloat16_rn(v.x - __bfloat162float(hx));
    l0.y = __float2bfloat16_rn(v.y - __bfloat162float(hy));
    l1.x = __float2bfloat16_rn(v.z - __bfloat162float(hz));
    l1.y = __float2bfloat16_rn(v.w - __bfloat162float(hw));
    ((__nv_bfloat162*)hi)[i*2+0] = h0;
    ((__nv_bfloat162*)hi)[i*2+1] = h1;
    ((__nv_bfloat162*)lo)[i*2+0] = l0;
    ((__nv_bfloat162*)lo)[i*2+1] = l1;
}

// ============================================================================
// bf16-split tensor-core GEMM:
//   C[M=4096, N=1024] = A[M,K] @ W[N,K]^T + bias,  via 3x mma.sync bf16
//   (hi*hi + hi*lo + lo*hi), fp32 accumulate.
// CTA 128x128, BK=32, cp.async double buffer, 8 warps of 64x32.
// SMEM tiles: row pitch 80B (32 bf16 + 8 pad) -> conflict-free frag loads.
// ============================================================================
#define PITCH   80
#define T_AH    0
#define T_AL    10240
#define T_BH    20480
#define T_BL    30720
#define STAGE   40960
#define GEMM_SMEM (2*STAGE)

__device__ __forceinline__ void load_chunk_g(
    uint32_t sbase, int buf,
    const __nv_bfloat16* __restrict__ Ah, const __nv_bfloat16* __restrict__ Al,
    const __nv_bfloat16* __restrict__ Bh, const __nv_bfloat16* __restrict__ Bl,
    int bm, int bn, int k0, int tid)
{
    uint32_t s = sbase + buf * STAGE;
    #pragma unroll
    for (int it = 0; it < 2; ++it) {
        int idx = tid + it * 256;          // 0..511
        int row = idx >> 2;                // 0..127
        int qq  = idx & 3;                 // 0..3
        uint32_t doff = (uint32_t)(row * PITCH + qq * 16);
        size_t ga = (size_t)(bm + row) * DD + k0 + qq * 8;
        size_t gb = (size_t)(bn + row) * DD + k0 + qq * 8;
        cp_async16(s + T_AH + doff, Ah + ga);
        cp_async16(s + T_AL + doff, Al + ga);
        cp_async16(s + T_BH + doff, Bh + gb);
        cp_async16(s + T_BL + doff, Bl + gb);
    }
    CP_COMMIT();
}

__global__ __launch_bounds__(256, 1) void gemm_split(
    const __nv_bfloat16* __restrict__ Ah, const __nv_bfloat16* __restrict__ Al,
    const __nv_bfloat16* __restrict__ Bh, const __nv_bfloat16* __restrict__ Bl,
    const float* __restrict__ bias, float* __restrict__ C)
{
    extern __shared__ char smem[];
    const uint32_t sbase = smem_u32(smem);
    const int tid  = threadIdx.x;
    const int wid  = tid >> 5;
    const int lane = tid & 31;
    const int warp_m = wid & 1;        // 0..1
    const int warp_n = wid >> 1;       // 0..3
    const int bm = blockIdx.y * 128;
    const int bn = blockIdx.x * 128;

    float c[4][4][4];
    #pragma unroll
    for (int i = 0; i < 4; ++i)
        #pragma unroll
        for (int j = 0; j < 4; ++j)
            #pragma unroll
            for (int e = 0; e < 4; ++e) c[i][j][e] = 0.f;

    // prologue
    load_chunk_g(sbase, 0, Ah, Al, Bh, Bl, bm, bn, 0,  tid);
    load_chunk_g(sbase, 1, Ah, Al, Bh, Bl, bm, bn, 32, tid);

    const int NCHUNK = DD / 32;  // 32
    for (int i = 0; i < NCHUNK; ++i) {
        const int buf = i & 1;
        if (i < NCHUNK - 1) asm volatile("cp.async.wait_group 1;" ::: "memory");
        else                asm volatile("cp.async.wait_group 0;" ::: "memory");
        __syncthreads();

        const char* base = smem + buf * STAGE;
        #pragma unroll
        for (int ks = 0; ks < 2; ++ks) {
            const int kb = ks * 32 + (lane & 3) * 4;   // byte offset in row
            uint32_t ah[4][4], al[4][4], bh[4][2], bl[4][2];
            #pragma unroll
            for (int mf = 0; mf < 4; ++mf) {
                int r = warp_m * 64 + mf * 16 + (lane >> 2);
                const char* pa = base + T_AH + r * PITCH + kb;
                ah[mf][0] = *(const uint32_t*)(pa);
                ah[mf][1] = *(const uint32_t*)(pa + 8 * PITCH);
                ah[mf][2] = *(const uint32_t*)(pa + 16);
                ah[mf][3] = *(const uint32_t*)(pa + 8 * PITCH + 16);
                const char* pl = base + T_AL + r * PITCH + kb;
                al[mf][0] = *(const uint32_t*)(pl);
                al[mf][1] = *(const uint32_t*)(pl + 8 * PITCH);
                al[mf][2] = *(const uint32_t*)(pl + 16);
                al[mf][3] = *(const uint32_t*)(pl + 8 * PITCH + 16);
            }
            #pragma unroll
            for (int nf = 0; nf < 4; ++nf) {
                int r = warp_n * 32 + nf * 8 + (lane >> 2);
                const char* pb = base + T_BH + r * PITCH + kb;
                bh[nf][0] = *(const uint32_t*)(pb);
                bh[nf][1] = *(const uint32_t*)(pb + 16);
                const char* pl = base + T_BL + r * PITCH + kb;
                bl[nf][0] = *(const uint32_t*)(pl);
                bl[nf][1] = *(const uint32_t*)(pl + 16);
            }
            #pragma unroll
            for (int mf = 0; mf < 4; ++mf)
                #pragma unroll
                for (int nf = 0; nf < 4; ++nf) {
                    MMA_BF16(c[mf][nf], ah[mf], bh[nf]);
                    MMA_BF16(c[mf][nf], ah[mf], bl[nf]);
                    MMA_BF16(c[mf][nf], al[mf], bh[nf]);
                }
        }
        __syncthreads();
        if (i + 2 < NCHUNK)
            load_chunk_g(sbase, buf, Ah, Al, Bh, Bl, bm, bn, (i + 2) * 32, tid);
    }

    // epilogue: bias add + fp32 store
    #pragma unroll
    for (int mf = 0; mf < 4; ++mf) {
        int m0 = bm + warp_m * 64 + mf * 16 + (lane >> 2);
        #pragma unroll
        for (int nf = 0; nf < 4; ++nf) {
            int n = bn + warp_n * 32 + nf * 8 + (lane & 3) * 2;
            float2 bb = *(const float2*)&bias[n];
            float2 o0, o1;
            o0.x = c[mf][nf][0] + bb.x;  o0.y = c[mf][nf][1] + bb.y;
            o1.x = c[mf][nf][2] + bb.x;  o1.y = c[mf][nf][3] + bb.y;
            *(float2*)&C[(size_t)m0 * DD + n]       = o0;
            *(float2*)&C[(size_t)(m0 + 8) * DD + n] = o1;
        }
    }
}

// ============================================================================
// Flash attention (fp32 SIMT, online softmax, NO 1/sqrt(dk) scaling)
// Output written with the reference's buggy swapaxes layout:
//   X[((h*B + b)*S + s)*DH + d]
// ============================================================================
#define QS_PITCH 68
#define PS_PITCH 68

__global__ __launch_bounds__(256) void attn_kernel(
    const float* __restrict__ Qp, const float* __restrict__ Kp,
    const float* __restrict__ Vp, float* __restrict__ X)
{
    extern __shared__ float sm[];
    float* Qs  = sm;                        // 64 x 68
    float* Kst = Qs  + 64 * QS_PITCH;       // 64 x 64  [d][key]
    float* Vs  = Kst + 64 * 64;             // 64 x 64  [key][d]
    float* Ps  = Vs  + 64 * 64;             // 64 x 68

    const int tid = threadIdx.x;
    const int tx = tid & 15;
    const int ty = tid >> 4;
    const int q0 = blockIdx.x * 64;
    const int bh = blockIdx.y;
    const int b  = bh >> 4;
    const int h  = bh & 15;

    const float* Qbase = Qp + (size_t)b * SS * DD + h * DHH;
    const float* Kbase = Kp + (size_t)b * SS * DD + h * DHH;
    const float* Vbase = Vp + (size_t)b * SS * DD + h * DHH;

    #pragma unroll
    for (int u = 0; u < 4; ++u) {
        int f  = tid + u * 256;
        int r  = f >> 4;
        int c4 = f & 15;
        float4 q4 = *(const float4*)&Qbase[(size_t)(q0 + r) * DD + c4 * 4];
        *(float4*)&Qs[r * QS_PITCH + c4 * 4] = q4;
    }

    float m_i[4], l_i[4], o[4][4];
    #pragma unroll
    for (int i = 0; i < 4; ++i) {
        m_i[i] = -1e30f; l_i[i] = 0.f;
        #pragma unroll
        for (int j = 0; j < 4; ++j) o[i][j] = 0.f;
    }

    for (int kt = 0; kt < SS / 64; ++kt) {
        #pragma unroll
        for (int u = 0; u < 4; ++u) {
            int f  = tid + u * 256;
            int r  = f >> 4;
            int c4 = f & 15;
            float4 k4 = *(const float4*)&Kbase[(size_t)(kt*64 + r) * DD + c4 * 4];
            Kst[(c4*4+0)*64 + r] = k4.x;
            Kst[(c4*4+1)*64 + r] = k4.y;
            Kst[(c4*4+2)*64 + r] = k4.z;
            Kst[(c4*4+3)*64 + r] = k4.w;
            float4 v4 = *(const float4*)&Vbase[(size_t)(kt*64 + r) * DD + c4 * 4];
            *(float4*)&Vs[r * 64 + c4 * 4] = v4;
        }
        __syncthreads();

        float s[4][4];
        #pragma unroll
        for (int i = 0; i < 4; ++i)
            #pragma unroll
            for (int j = 0; j < 4; ++j) s[i][j] = 0.f;

        #pragma unroll 8
        for (int d = 0; d < 64; ++d) {
            float4 kv = *(const float4*)&Kst[d * 64 + tx * 4];
            #pragma unroll
            for (int i = 0; i < 4; ++i) {
                float qv = Qs[(ty*4 + i) * QS_PITCH + d];
                s[i][0] += qv * kv.x;
                s[i][1] += qv * kv.y;
                s[i][2] += qv * kv.z;
                s[i][3] += qv * kv.w;
            }
        }

        #pragma unroll
        for (int i = 0; i < 4; ++i) {
            float mx = fmaxf(fmaxf(s[i][0], s[i][1]), fmaxf(s[i][2], s[i][3]));
            #pragma unroll
            for (int off = 1; off < 16; off <<= 1)
                mx = fmaxf(mx, __shfl_xor_sync(0xffffffffu, mx, off));
            float m_new = fmaxf(m_i[i], mx);
            float scale = __expf(m_i[i] - m_new);
            float p0 = __expf(s[i][0] - m_new);
            float p1 = __expf(s[i][1] - m_new);
            float p2 = __expf(s[i][2] - m_new);
            float p3 = __expf(s[i][3] - m_new);
            float ps = p0 + p1 + p2 + p3;
            #pragma unroll
            for (int off = 1; off < 16; off <<= 1)
                ps += __shfl_xor_sync(0xffffffffu, ps, off);
            l_i[i] = l_i[i] * scale + ps;
            m_i[i] = m_new;
            #pragma unroll
            for (int j = 0; j < 4; ++j) o[i][j] *= scale;
            float4 p4 = make_float4(p0, p1, p2, p3);
            *(float4*)&Ps[(ty*4 + i) * PS_PITCH + tx * 4] = p4;
        }
        __syncthreads();

        #pragma unroll 8
        for (int k = 0; k < 64; ++k) {
            float4 vv = *(const float4*)&Vs[k * 64 + tx * 4];
            #pragma unroll
            for (int i = 0; i < 4; ++i) {
                float pv = Ps[(ty*4 + i) * PS_PITCH + k];
                o[i][0] += pv * vv.x;
                o[i][1] += pv * vv.y;
                o[i][2] += pv * vv.z;
                o[i][3] += pv * vv.w;
            }
        }
        __syncthreads();
    }

    #pragma unroll
    for (int i = 0; i < 4; ++i) {
        int r = ty*4 + i;
        float inv = 1.0f / l_i[i];
        float4 ov = make_float4(o[i][0]*inv, o[i][1]*inv, o[i][2]*inv, o[i][3]*inv);
        size_t idx = (((size_t)(h * BB + b) * SS) + (q0 + r)) * DHH + tx * 4;
        *(float4*)&X[idx] = ov;
    }
}

#define ATTN_SMEM ((64*QS_PITCH + 64*64 + 64*64 + 64*PS_PITCH) * (int)sizeof(float))

extern "C" void kernel_launch(void* const* d_in, const int* in_sizes, int n_in,
                              void* d_out, int out_size)
{
    const float* q  = (const float*)d_in[0];
    const float* k  = (const float*)d_in[1];
    const float* v  = (const float*)d_in[2];
    const float* wq = (const float*)d_in[3];
    const float* bq = (const float*)d_in[4];
    const float* wk = (const float*)d_in[5];
    const float* bk = (const float*)d_in[6];
    const float* wv = (const float*)d_in[7];
    const float* bv = (const float*)d_in[8];
    const float* wo = (const float*)d_in[9];
    const float* bo = (const float*)d_in[10];
    float* out = (float*)d_out;

    float *Qp, *Kp, *Vp, *X;
    __nv_bfloat16 *Whi, *Wlo, *Ahi, *Alo;
    cudaGetSymbolAddress((void**)&Qp,  g_Qp);
    cudaGetSymbolAddress((void**)&Kp,  g_Kp);
    cudaGetSymbolAddress((void**)&Vp,  g_Vp);
    cudaGetSymbolAddress((void**)&X,   g_X);
    cudaGetSymbolAddress((void**)&Whi, g_Whi);
    cudaGetSymbolAddress((void**)&Wlo, g_Wlo);
    cudaGetSymbolAddress((void**)&Ahi, g_Ahi);
    cudaGetSymbolAddress((void**)&Alo, g_Alo);

    cudaFuncSetAttribute(attn_kernel,
                         cudaFuncAttributeMaxDynamicSharedMemorySize, ATTN_SMEM);
    cudaFuncSetAttribute(gemm_split,
                         cudaFuncAttributeMaxDynamicSharedMemorySize, GEMM_SMEM);

    // Weights: transpose to K-major + bf16 hi/lo split
    dim3 tGrid(DD / 32, DD / 32), tBlk(32, 8);
    trans_split_kernel<<<tGrid, tBlk>>>(wq, Whi + 0*DD*DD, Wlo + 0*DD*DD);
    trans_split_kernel<<<tGrid, tBlk>>>(wk, Whi + 1*DD*DD, Wlo + 1*DD*DD);
    trans_split_kernel<<<tGrid, tBlk>>>(wv, Whi + 2*DD*DD, Wlo + 2*DD*DD);
    trans_split_kernel<<<tGrid, tBlk>>>(wo, Whi + 3*DD*DD, Wlo + 3*DD*DD);

    const int n4 = MTOT * DD / 4;
    dim3 sGrid((n4 + 255) / 256);
    dim3 gGrid(DD / 128, MTOT / 128);   // (8, 32)

    // Q projection
    split_kernel<<<sGrid, 256>>>(q, Ahi, Alo, n4);
    gemm_split<<<gGrid, 256, GEMM_SMEM>>>(Ahi, Alo, Whi + 0*DD*DD, Wlo + 0*DD*DD, bq, Qp);
    // K projection
    split_kernel<<<sGrid, 256>>>(k, Ahi, Alo, n4);
    gemm_split<<<gGrid, 256, GEMM_SMEM>>>(Ahi, Alo, Whi + 1*DD*DD, Wlo + 1*DD*DD, bk, Kp);
    // V projection
    split_kernel<<<sGrid, 256>>>(v, Ahi, Alo, n4);
    gemm_split<<<gGrid, 256, GEMM_SMEM>>>(Ahi, Alo, Whi + 2*DD*DD, Wlo + 2*DD*DD, bv, Vp);

    // Attention (fp32 SIMT)
    dim3 aGrid(SS / 64, BB * HH);       // (32, 32)
    attn_kernel<<<aGrid, 256, ATTN_SMEM>>>(Qp, Kp, Vp, X);

    // Output projection
    split_kernel<<<sGrid, 256>>>(X, Ahi, Alo, n4);
    gemm_split<<<gGrid, 256, GEMM_SMEM>>>(Ahi, Alo, Whi + 3*DD*DD, Wlo + 3*DD*DD, bo, out);
}